// round 3
// baseline (speedup 1.0000x reference)
#include <cuda_runtime.h>
#include <cuda_fp16.h>

// B=512, T=256, D=H=128, gates=512.
// 256 CTAs x 256 threads, 2 CTAs/SM. Each CTA: 2 batch rows, full recurrence.
// Thread t computes gate columns t and t+256 for both rows.
// (x,h) packed float2 in smem [k][row]; weights packed half2 (Wih,Whh) k-major.

#define Tt 256

__device__ __align__(16) __half2 g_E0[128 * 512];
__device__ __align__(16) __half2 g_E1[128 * 512];
__device__ __align__(16) __half2 g_D0[128 * 512];
__device__ __align__(16) __half2 g_D1[128 * 512];
__device__ __align__(16) float   g_OW[128 * 128];   // out_W transposed [k][d]
__device__ float g_bE0[512], g_bE1[512], g_bD0[512], g_bD1[512];

__global__ void prep_kernel(
    const float* __restrict__ eW0, const float* __restrict__ eU0,
    const float* __restrict__ ebi0, const float* __restrict__ ebh0,
    const float* __restrict__ eW1, const float* __restrict__ eU1,
    const float* __restrict__ ebi1, const float* __restrict__ ebh1,
    const float* __restrict__ dW0, const float* __restrict__ dU0,
    const float* __restrict__ dbi0, const float* __restrict__ dbh0,
    const float* __restrict__ dW1, const float* __restrict__ dU1,
    const float* __restrict__ dbi1, const float* __restrict__ dbh1,
    const float* __restrict__ oW)
{
    int idx = blockIdx.x * blockDim.x + threadIdx.x;   // 0..65535
    int k = idx >> 9;
    int j = idx & 511;
    int src = j * 128 + k;
    g_E0[idx] = __floats2half2_rn(eW0[src], eU0[src]);
    g_E1[idx] = __floats2half2_rn(eW1[src], eU1[src]);
    g_D0[idx] = __floats2half2_rn(dW0[src], dU0[src]);
    g_D1[idx] = __floats2half2_rn(dW1[src], dU1[src]);
    if (idx < 128 * 128) {
        int kk = idx >> 7, d = idx & 127;
        g_OW[kk * 128 + d] = oW[d * 128 + kk];
    }
    if (idx < 512) {
        g_bE0[idx] = ebi0[idx] + ebh0[idx];
        g_bE1[idx] = ebi1[idx] + ebh1[idx];
        g_bD0[idx] = dbi0[idx] + dbh0[idx];
        g_bD1[idx] = dbi1[idx] + dbh1[idx];
    }
}

__device__ __forceinline__ float sigf(float v)   { return 1.0f / (1.0f + __expf(-v)); }
__device__ __forceinline__ float tanhfa(float v) { return 1.0f - 2.0f / (__expf(2.0f * v) + 1.0f); }

// One LSTM layer step for 2 rows. xin: [k][row] float2 (input, h).
// MODE 0: layer0  -> write h to xh0[.].y (next-step h) and xh1[.].x (layer1 in)
// MODE 1: enc L1  -> write h to xh1[.].y
// MODE 2: dec L1  -> write h to xh1[.].y and xh0[.].x (feedback input)
template<int MODE>
__device__ __forceinline__ void layer_step(
    const __half2* __restrict__ Wp, const float* __restrict__ bias,
    const float2* __restrict__ xin, float* __restrict__ cst,
    float2* __restrict__ xh0, float2* __restrict__ xh1,
    float* __restrict__ g, int tid, int bb, int nn)
{
    float a0A = bias[tid];
    float a0B = bias[tid + 256];
    float a1A = a0A, a1B = a0B;
    const float4*  xv = (const float4*)xin;          // one 16B load = both rows at k
    const __half2* w  = Wp + tid;

#pragma unroll 8
    for (int k = 0; k < 128; k++) {
        float4 p  = xv[k];                           // (x0,h0,x1,h1) at this k
        float2 wA = __half22float2(w[k * 512]);
        float2 wB = __half22float2(w[k * 512 + 256]);
        a0A = fmaf(wA.x, p.x, a0A); a0A = fmaf(wA.y, p.y, a0A);
        a1A = fmaf(wA.x, p.z, a1A); a1A = fmaf(wA.y, p.w, a1A);
        a0B = fmaf(wB.x, p.x, a0B); a0B = fmaf(wB.y, p.y, a0B);
        a1B = fmaf(wB.x, p.z, a1B); a1B = fmaf(wB.y, p.w, a1B);
    }
    g[tid]       = a0A;  g[tid + 256]       = a0B;
    g[512 + tid] = a1A;  g[512 + tid + 256] = a1B;
    __syncthreads();

    // activation: thread (bb, nn)
    float gi = g[bb * 512 + nn];
    float gf = g[bb * 512 + nn + 128];
    float gg = g[bb * 512 + nn + 256];
    float go = g[bb * 512 + nn + 384];
    float c  = sigf(gf) * cst[bb * 128 + nn] + sigf(gi) * tanhfa(gg);
    float h  = sigf(go) * tanhfa(c);
    cst[bb * 128 + nn] = c;
    if (MODE == 0) { xh0[nn * 2 + bb].y = h; xh1[nn * 2 + bb].x = h; }
    else           { xh1[nn * 2 + bb].y = h;
                     if (MODE == 2) xh0[nn * 2 + bb].x = h; }
    __syncthreads();
}

__global__ void __launch_bounds__(256, 2) lstm_main(
    const float* __restrict__ x, const float* __restrict__ out_b,
    float* __restrict__ out)
{
    __shared__ __align__(16) float2 s_xh0[128 * 2];  // [k][row]: (in0, h0)
    __shared__ __align__(16) float2 s_xh1[128 * 2];  // [k][row]: (h0_new, h1)
    __shared__ float s_c0[2 * 128], s_c1[2 * 128];
    __shared__ float s_g[2 * 512];

    const int tid = threadIdx.x;
    const int bb  = tid >> 7;       // row 0/1
    const int nn  = tid & 127;      // hidden unit
    const int bg  = blockIdx.x * 2;

    s_xh0[nn * 2 + bb] = make_float2(0.f, 0.f);
    s_xh1[nn * 2 + bb] = make_float2(0.f, 0.f);
    s_c0[bb * 128 + nn] = 0.f;
    s_c1[bb * 128 + nn] = 0.f;
    __syncthreads();

    // ------------------------------ encoder ------------------------------
    const float* xbase = x + (size_t)(bg + bb) * (Tt * 128) + nn;
    for (int t = 0; t < Tt; t++) {
        s_xh0[nn * 2 + bb].x = xbase[t * 128];
        __syncthreads();
        layer_step<0>(g_E0, g_bE0, s_xh0, s_c0, s_xh0, s_xh1, s_g, tid, bb, nn);
        layer_step<1>(g_E1, g_bE1, s_xh1, s_c1, s_xh0, s_xh1, s_g, tid, bb, nn);
    }

    // phase switch: x0 = final h1; all decoder states zero
    float x0v = s_xh1[nn * 2 + bb].y;
    __syncthreads();
    s_xh0[nn * 2 + bb] = make_float2(x0v, 0.f);
    s_xh1[nn * 2 + bb] = make_float2(0.f, 0.f);
    s_c0[bb * 128 + nn] = 0.f;
    s_c1[bb * 128 + nn] = 0.f;
    __syncthreads();

    // ------------------------------ decoder ------------------------------
    float* obase = out + (size_t)(bg + bb) * (Tt * 128) + nn;
    const float ob = out_b[nn];
    for (int t = 0; t < Tt; t++) {
        layer_step<0>(g_D0, g_bD0, s_xh0, s_c0, s_xh0, s_xh1, s_g, tid, bb, nn);
        layer_step<2>(g_D1, g_bD1, s_xh1, s_c1, s_xh0, s_xh1, s_g, tid, bb, nn);

        // out[b,t,nn] = h1[b,:] . out_W[nn,:] + out_b[nn]
        float acc = ob;
#pragma unroll 8
        for (int k = 0; k < 128; k++)
            acc = fmaf(s_xh1[k * 2 + bb].y, g_OW[k * 128 + nn], acc);
        obase[t * 128] = acc;
    }
}

extern "C" void kernel_launch(void* const* d_in, const int* in_sizes, int n_in,
                              void* d_out, int out_size)
{
    const float* x    = (const float*)d_in[0];
    const float* eW0  = (const float*)d_in[1];
    const float* eU0  = (const float*)d_in[2];
    const float* ebi0 = (const float*)d_in[3];
    const float* ebh0 = (const float*)d_in[4];
    const float* eW1  = (const float*)d_in[5];
    const float* eU1  = (const float*)d_in[6];
    const float* ebi1 = (const float*)d_in[7];
    const float* ebh1 = (const float*)d_in[8];
    const float* dW0  = (const float*)d_in[9];
    const float* dU0  = (const float*)d_in[10];
    const float* dbi0 = (const float*)d_in[11];
    const float* dbh0 = (const float*)d_in[12];
    const float* dW1  = (const float*)d_in[13];
    const float* dU1  = (const float*)d_in[14];
    const float* dbi1 = (const float*)d_in[15];
    const float* dbh1 = (const float*)d_in[16];
    const float* oW   = (const float*)d_in[17];
    const float* ob   = (const float*)d_in[18];

    prep_kernel<<<128, 512>>>(eW0, eU0, ebi0, ebh0,
                              eW1, eU1, ebi1, ebh1,
                              dW0, dU0, dbi0, dbh0,
                              dW1, dU1, dbi1, dbh1, oW);
    lstm_main<<<256, 256>>>(x, ob, (float*)d_out);
}

// round 4
// speedup vs baseline: 1.0026x; 1.0026x over previous
#include <cuda_runtime.h>
#include <cuda_fp16.h>

// B=512, T=256, D=H=128, gates=512.
// 256 CTAs x 256 threads, 2 CTAs/SM. Each CTA: 2 batch rows, full recurrence.
// Thread t computes gate columns t and t+256 for both rows.
// (x,h) packed float2 in smem [k][row]; weights packed half2 (Wih,Whh) k-major.

#define Tt 256

__device__ __align__(16) __half2 g_E0[128 * 512];
__device__ __align__(16) __half2 g_E1[128 * 512];
__device__ __align__(16) __half2 g_D0[128 * 512];
__device__ __align__(16) __half2 g_D1[128 * 512];
__device__ __align__(16) float   g_OW[128 * 128];   // out_W transposed [k][d]
__device__ float g_bE0[512], g_bE1[512], g_bD0[512], g_bD1[512];

__global__ void prep_kernel(
    const float* __restrict__ eW0, const float* __restrict__ eU0,
    const float* __restrict__ ebi0, const float* __restrict__ ebh0,
    const float* __restrict__ eW1, const float* __restrict__ eU1,
    const float* __restrict__ ebi1, const float* __restrict__ ebh1,
    const float* __restrict__ dW0, const float* __restrict__ dU0,
    const float* __restrict__ dbi0, const float* __restrict__ dbh0,
    const float* __restrict__ dW1, const float* __restrict__ dU1,
    const float* __restrict__ dbi1, const float* __restrict__ dbh1,
    const float* __restrict__ oW)
{
    int idx = blockIdx.x * blockDim.x + threadIdx.x;   // 0..65535
    int k = idx >> 9;
    int j = idx & 511;
    int src = j * 128 + k;
    g_E0[idx] = __floats2half2_rn(eW0[src], eU0[src]);
    g_E1[idx] = __floats2half2_rn(eW1[src], eU1[src]);
    g_D0[idx] = __floats2half2_rn(dW0[src], dU0[src]);
    g_D1[idx] = __floats2half2_rn(dW1[src], dU1[src]);
    if (idx < 128 * 128) {
        int kk = idx >> 7, d = idx & 127;
        g_OW[kk * 128 + d] = oW[d * 128 + kk];
    }
    if (idx < 512) {
        g_bE0[idx] = ebi0[idx] + ebh0[idx];
        g_bE1[idx] = ebi1[idx] + ebh1[idx];
        g_bD0[idx] = dbi0[idx] + dbh0[idx];
        g_bD1[idx] = dbi1[idx] + dbh1[idx];
    }
}

__device__ __forceinline__ float sigf(float v)   { return 1.0f / (1.0f + __expf(-v)); }
__device__ __forceinline__ float tanhfa(float v) { return 1.0f - 2.0f / (__expf(2.0f * v) + 1.0f); }

// One LSTM layer step for 2 rows. xin: [k][row] float2 (input, h).
// MODE 0: layer0  -> write h to xh0[.].y (next-step h) and xh1[.].x (layer1 in)
// MODE 1: enc L1  -> write h to xh1[.].y
// MODE 2: dec L1  -> write h to xh1[.].y and xh0[.].x (feedback input)
template<int MODE>
__device__ __forceinline__ void layer_step(
    const __half2* __restrict__ Wp, const float* __restrict__ bias,
    const float2* __restrict__ xin, float* __restrict__ cst,
    float2* __restrict__ xh0, float2* __restrict__ xh1,
    float* __restrict__ g, int tid, int bb, int nn)
{
    float a0A = bias[tid];
    float a0B = bias[tid + 256];
    float a1A = a0A, a1B = a0B;
    const float4*  xv = (const float4*)xin;          // one 16B load = both rows at k
    const __half2* w  = Wp + tid;

#pragma unroll 8
    for (int k = 0; k < 128; k++) {
        float4 p  = xv[k];                           // (x0,h0,x1,h1) at this k
        float2 wA = __half22float2(w[k * 512]);
        float2 wB = __half22float2(w[k * 512 + 256]);
        a0A = fmaf(wA.x, p.x, a0A); a0A = fmaf(wA.y, p.y, a0A);
        a1A = fmaf(wA.x, p.z, a1A); a1A = fmaf(wA.y, p.w, a1A);
        a0B = fmaf(wB.x, p.x, a0B); a0B = fmaf(wB.y, p.y, a0B);
        a1B = fmaf(wB.x, p.z, a1B); a1B = fmaf(wB.y, p.w, a1B);
    }
    g[tid]       = a0A;  g[tid + 256]       = a0B;
    g[512 + tid] = a1A;  g[512 + tid + 256] = a1B;
    __syncthreads();

    // activation: thread (bb, nn)
    float gi = g[bb * 512 + nn];
    float gf = g[bb * 512 + nn + 128];
    float gg = g[bb * 512 + nn + 256];
    float go = g[bb * 512 + nn + 384];
    float c  = sigf(gf) * cst[bb * 128 + nn] + sigf(gi) * tanhfa(gg);
    float h  = sigf(go) * tanhfa(c);
    cst[bb * 128 + nn] = c;
    if (MODE == 0) { xh0[nn * 2 + bb].y = h; xh1[nn * 2 + bb].x = h; }
    else           { xh1[nn * 2 + bb].y = h;
                     if (MODE == 2) xh0[nn * 2 + bb].x = h; }
    __syncthreads();
}

__global__ void __launch_bounds__(256, 2) lstm_main(
    const float* __restrict__ x, const float* __restrict__ out_b,
    float* __restrict__ out)
{
    __shared__ __align__(16) float2 s_xh0[128 * 2];  // [k][row]: (in0, h0)
    __shared__ __align__(16) float2 s_xh1[128 * 2];  // [k][row]: (h0_new, h1)
    __shared__ float s_c0[2 * 128], s_c1[2 * 128];
    __shared__ float s_g[2 * 512];

    const int tid = threadIdx.x;
    const int bb  = tid >> 7;       // row 0/1
    const int nn  = tid & 127;      // hidden unit
    const int bg  = blockIdx.x * 2;

    s_xh0[nn * 2 + bb] = make_float2(0.f, 0.f);
    s_xh1[nn * 2 + bb] = make_float2(0.f, 0.f);
    s_c0[bb * 128 + nn] = 0.f;
    s_c1[bb * 128 + nn] = 0.f;
    __syncthreads();

    // ------------------------------ encoder ------------------------------
    const float* xbase = x + (size_t)(bg + bb) * (Tt * 128) + nn;
    for (int t = 0; t < Tt; t++) {
        s_xh0[nn * 2 + bb].x = xbase[t * 128];
        __syncthreads();
        layer_step<0>(g_E0, g_bE0, s_xh0, s_c0, s_xh0, s_xh1, s_g, tid, bb, nn);
        layer_step<1>(g_E1, g_bE1, s_xh1, s_c1, s_xh0, s_xh1, s_g, tid, bb, nn);
    }

    // phase switch: x0 = final h1; all decoder states zero
    float x0v = s_xh1[nn * 2 + bb].y;
    __syncthreads();
    s_xh0[nn * 2 + bb] = make_float2(x0v, 0.f);
    s_xh1[nn * 2 + bb] = make_float2(0.f, 0.f);
    s_c0[bb * 128 + nn] = 0.f;
    s_c1[bb * 128 + nn] = 0.f;
    __syncthreads();

    // ------------------------------ decoder ------------------------------
    float* obase = out + (size_t)(bg + bb) * (Tt * 128) + nn;
    const float ob = out_b[nn];
    for (int t = 0; t < Tt; t++) {
        layer_step<0>(g_D0, g_bD0, s_xh0, s_c0, s_xh0, s_xh1, s_g, tid, bb, nn);
        layer_step<2>(g_D1, g_bD1, s_xh1, s_c1, s_xh0, s_xh1, s_g, tid, bb, nn);

        // out[b,t,nn] = h1[b,:] . out_W[nn,:] + out_b[nn]
        float acc = ob;
#pragma unroll 8
        for (int k = 0; k < 128; k++)
            acc = fmaf(s_xh1[k * 2 + bb].y, g_OW[k * 128 + nn], acc);
        obase[t * 128] = acc;
    }
}

extern "C" void kernel_launch(void* const* d_in, const int* in_sizes, int n_in,
                              void* d_out, int out_size)
{
    const float* x    = (const float*)d_in[0];
    const float* eW0  = (const float*)d_in[1];
    const float* eU0  = (const float*)d_in[2];
    const float* ebi0 = (const float*)d_in[3];
    const float* ebh0 = (const float*)d_in[4];
    const float* eW1  = (const float*)d_in[5];
    const float* eU1  = (const float*)d_in[6];
    const float* ebi1 = (const float*)d_in[7];
    const float* ebh1 = (const float*)d_in[8];
    const float* dW0  = (const float*)d_in[9];
    const float* dU0  = (const float*)d_in[10];
    const float* dbi0 = (const float*)d_in[11];
    const float* dbh0 = (const float*)d_in[12];
    const float* dW1  = (const float*)d_in[13];
    const float* dU1  = (const float*)d_in[14];
    const float* dbi1 = (const float*)d_in[15];
    const float* dbh1 = (const float*)d_in[16];
    const float* oW   = (const float*)d_in[17];
    const float* ob   = (const float*)d_in[18];

    prep_kernel<<<128, 512>>>(eW0, eU0, ebi0, ebh0,
                              eW1, eU1, ebi1, ebh1,
                              dW0, dU0, dbi0, dbh0,
                              dW1, dU1, dbi1, dbh1, oW);
    lstm_main<<<256, 256>>>(x, ob, (float*)d_out);
}

// round 5
// speedup vs baseline: 1.4111x; 1.4075x over previous
#include <cuda_runtime.h>
#include <cuda_fp16.h>

// B=512,T=256,D=H=128. 128 CTAs x 512 threads, 4 batch rows/CTA.
// GEMM thread j: gate column j, 4 rows, HFMA2 lanes=(Wih*x, Whh*h),
// fp16 acc spilled to packed-f32x2 every 4 k. Act thread (bb,nn): c in regs.

#define Tt 256

__device__ __align__(16) __half2 g_E0[128 * 512];
__device__ __align__(16) __half2 g_E1[128 * 512];
__device__ __align__(16) __half2 g_D0[128 * 512];
__device__ __align__(16) __half2 g_D1[128 * 512];
__device__ __align__(16) float   g_OW[128 * 128];
__device__ float g_bE0[512], g_bE1[512], g_bD0[512], g_bD1[512];

__global__ void prep_kernel(
    const float* __restrict__ eW0, const float* __restrict__ eU0,
    const float* __restrict__ ebi0, const float* __restrict__ ebh0,
    const float* __restrict__ eW1, const float* __restrict__ eU1,
    const float* __restrict__ ebi1, const float* __restrict__ ebh1,
    const float* __restrict__ dW0, const float* __restrict__ dU0,
    const float* __restrict__ dbi0, const float* __restrict__ dbh0,
    const float* __restrict__ dW1, const float* __restrict__ dU1,
    const float* __restrict__ dbi1, const float* __restrict__ dbh1,
    const float* __restrict__ oW)
{
    int idx = blockIdx.x * blockDim.x + threadIdx.x;  // 0..65535
    int k = idx >> 9, j = idx & 511;
    int src = j * 128 + k;
    g_E0[idx] = __floats2half2_rn(eW0[src], eU0[src]);
    g_E1[idx] = __floats2half2_rn(eW1[src], eU1[src]);
    g_D0[idx] = __floats2half2_rn(dW0[src], dU0[src]);
    g_D1[idx] = __floats2half2_rn(dW1[src], dU1[src]);
    if (idx < 128 * 128) {
        int kk = idx >> 7, d = idx & 127;
        g_OW[kk * 128 + d] = oW[d * 128 + kk];
    }
    if (idx < 512) {
        g_bE0[idx] = ebi0[idx] + ebh0[idx];
        g_bE1[idx] = ebi1[idx] + ebh1[idx];
        g_bD0[idx] = dbi0[idx] + dbh0[idx];
        g_bD1[idx] = dbi1[idx] + dbh1[idx];
    }
}

__device__ __forceinline__ float sigf(float v)   { return 1.0f / (1.0f + __expf(-v)); }
__device__ __forceinline__ float tanhfa(float v) { return 1.0f - 2.0f / (__expf(2.0f * v) + 1.0f); }

typedef unsigned long long u64;

__device__ __forceinline__ void spill(u64& acc, __half2 a) {
    float lo = __low2float(a), hi = __high2float(a);
    u64 p;
    asm("mov.b64 %0, {%1,%2};" : "=l"(p) : "f"(lo), "f"(hi));
    asm("add.rn.f32x2 %0, %1, %2;" : "=l"(acc) : "l"(acc), "l"(p));
}
__device__ __forceinline__ float fin(u64 acc, float b) {
    float lo, hi;
    asm("mov.b64 {%0,%1}, %2;" : "=f"(lo), "=f"(hi) : "l"(acc));
    return lo + hi + b;
}

// gates[r] = bias + sum_k (Wih[j,k]*x_r[k] + Whh[j,k]*h_r[k]); writes g[r*512].
__device__ __forceinline__ void gemm4(
    const __half2* __restrict__ Wp, const uint4* __restrict__ xh,
    float bias, float* __restrict__ g, int j)
{
    u64 A0 = 0, A1 = 0, A2 = 0, A3 = 0;
    const __half2* w = Wp + j;
    const __half2 z = __float2half2_rn(0.f);
#pragma unroll 8
    for (int c = 0; c < 32; c++) {
        __half2 a0 = z, a1 = z, a2 = z, a3 = z;
#pragma unroll
        for (int u = 0; u < 4; u++) {
            int k = c * 4 + u;
            uint4 xv = xh[k];                 // rows 0..3 (x,h) half2, broadcast
            __half2 wv = w[k * 512];
            a0 = __hfma2(wv, *(__half2*)&xv.x, a0);
            a1 = __hfma2(wv, *(__half2*)&xv.y, a1);
            a2 = __hfma2(wv, *(__half2*)&xv.z, a2);
            a3 = __hfma2(wv, *(__half2*)&xv.w, a3);
        }
        spill(A0, a0); spill(A1, a1); spill(A2, a2); spill(A3, a3);
    }
    g[0]    = fin(A0, bias);
    g[512]  = fin(A1, bias);
    g[1024] = fin(A2, bias);
    g[1536] = fin(A3, bias);
}

__device__ __forceinline__ float2 act(const float* g, int bb, int nn, float c) {
    float gi = g[bb * 512 + nn],       gf = g[bb * 512 + nn + 128];
    float gg = g[bb * 512 + nn + 256], go = g[bb * 512 + nn + 384];
    float cn = sigf(gf) * c + sigf(gi) * tanhfa(gg);
    return make_float2(cn, sigf(go) * tanhfa(cn));
}

__global__ void __launch_bounds__(512, 1) lstm_main(
    const float* __restrict__ x, const float* __restrict__ out_b,
    float* __restrict__ out)
{
    __shared__ __align__(16) __half2 s_xh0[128 * 4];  // word nn*4+bb = (x,h)
    __shared__ __align__(16) __half2 s_xh1[128 * 4];
    __shared__ float s_g[4 * 512];
    __shared__ __align__(16) float s_h1f[4 * 128];

    const int j  = threadIdx.x;
    const int bb = j >> 7, nn = j & 127;
    const int bg = blockIdx.x * 4;
    __half* H0 = (__half*)s_xh0;
    __half* H1 = (__half*)s_xh1;
    const int ws = (nn * 4 + bb) * 2;   // half index of owned word

    const float bE0 = g_bE0[j], bE1 = g_bE1[j], bD0 = g_bD0[j], bD1 = g_bD1[j];
    const uint4* xh0 = (const uint4*)s_xh0;
    const uint4* xh1 = (const uint4*)s_xh1;
    float c0 = 0.f, c1 = 0.f;

    const float* xb = x + (size_t)(bg + bb) * (Tt * 128) + nn;
    s_xh0[nn * 4 + bb] = __float2half2_rn(0.f);
    s_xh1[nn * 4 + bb] = __float2half2_rn(0.f);
    H0[ws] = __float2half(xb[0]);
    __syncthreads();

    // ------------------------------ encoder ------------------------------
    for (int t = 0; t < Tt; t++) {
        gemm4(g_E0, xh0, bE0, s_g + j, j);
        __syncthreads();
        {
            float2 ch = act(s_g, bb, nn, c0); c0 = ch.x;
            __half hh = __float2half(ch.y);
            H0[ws + 1] = hh;                 // recurrent h0
            H1[ws]     = hh;                 // layer-1 input
        }
        __syncthreads();
        gemm4(g_E1, xh1, bE1, s_g + j, j);
        __syncthreads();
        {
            float2 ch = act(s_g, bb, nn, c1); c1 = ch.x;
            H1[ws + 1] = __float2half(ch.y);
            if (t + 1 < Tt) H0[ws] = __float2half(xb[(t + 1) * 128]);
        }
        __syncthreads();
    }

    // decoder init: x0 = final h1, everything else zero
    __half x0 = H1[ws + 1];
    s_xh0[nn * 4 + bb] = __halves2half2(x0, __float2half(0.f));
    s_xh1[nn * 4 + bb] = __float2half2_rn(0.f);
    c0 = 0.f; c1 = 0.f;
    __syncthreads();

    // ------------------------------ decoder ------------------------------
    float* ob_ = out + (size_t)(bg + bb) * (Tt * 128) + nn;
    const float obv = out_b[nn];
    for (int t = 0; t < Tt; t++) {
        gemm4(g_D0, xh0, bD0, s_g + j, j);
        __syncthreads();
        {
            float2 ch = act(s_g, bb, nn, c0); c0 = ch.x;
            __half hh = __float2half(ch.y);
            H0[ws + 1] = hh;
            H1[ws]     = hh;
        }
        __syncthreads();
        gemm4(g_D1, xh1, bD1, s_g + j, j);
        __syncthreads();
        {
            float2 ch = act(s_g, bb, nn, c1); c1 = ch.x;
            __half hh = __float2half(ch.y);
            H1[ws + 1] = hh;
            H0[ws]     = hh;                 // feedback input
            s_h1f[bb * 128 + nn] = ch.y;     // fp32 for projection
        }
        __syncthreads();

        float acc = obv;
        const float4* hv = (const float4*)(s_h1f + bb * 128);
#pragma unroll 8
        for (int kk = 0; kk < 32; kk++) {
            float4 h4 = hv[kk];
            acc = fmaf(h4.x, g_OW[(kk * 4 + 0) * 128 + nn], acc);
            acc = fmaf(h4.y, g_OW[(kk * 4 + 1) * 128 + nn], acc);
            acc = fmaf(h4.z, g_OW[(kk * 4 + 2) * 128 + nn], acc);
            acc = fmaf(h4.w, g_OW[(kk * 4 + 3) * 128 + nn], acc);
        }
        ob_[t * 128] = acc;
    }
}

extern "C" void kernel_launch(void* const* d_in, const int* in_sizes, int n_in,
                              void* d_out, int out_size)
{
    prep_kernel<<<128, 512>>>(
        (const float*)d_in[1],  (const float*)d_in[2],  (const float*)d_in[3],
        (const float*)d_in[4],  (const float*)d_in[5],  (const float*)d_in[6],
        (const float*)d_in[7],  (const float*)d_in[8],  (const float*)d_in[9],
        (const float*)d_in[10], (const float*)d_in[11], (const float*)d_in[12],
        (const float*)d_in[13], (const float*)d_in[14], (const float*)d_in[15],
        (const float*)d_in[16], (const float*)d_in[17]);
    lstm_main<<<128, 512>>>((const float*)d_in[0], (const float*)d_in[18],
                            (float*)d_out);
}

// round 6
// speedup vs baseline: 1.4391x; 1.0198x over previous
#include <cuda_runtime.h>
#include <cuda_fp16.h>

// B=512,T=256,D=H=128. 128 CTAs x 512 threads = 2 independent groups of 256
// (rows {0,1} and {2,3}) with separate smem + named barriers (ping-pong).
// Thread q of a group: gate cols q and q+256, 2 rows. HFMA2 lanes=(Wih*x,Whh*h),
// even/odd half2 accs spilled to packed-f32x2 every 8 k.

#define Tt 256
typedef unsigned long long u64;
typedef unsigned int u32;

// weights: [k][q] uint2 = ( half2(Wih[q,k],Whh[q,k]), half2(Wih[q+256,k],Whh[q+256,k]) )
__device__ __align__(16) uint2 g_E0[128 * 256];
__device__ __align__(16) uint2 g_E1[128 * 256];
__device__ __align__(16) uint2 g_D0[128 * 256];
__device__ __align__(16) uint2 g_D1[128 * 256];
__device__ __align__(16) float g_OW[128 * 128];
__device__ float g_bE0[512], g_bE1[512], g_bD0[512], g_bD1[512];

__device__ __forceinline__ u32 pk(float a, float b) {
    __half2 h = __floats2half2_rn(a, b); return *(u32*)&h;
}

__global__ void prep_kernel(
    const float* __restrict__ eW0, const float* __restrict__ eU0,
    const float* __restrict__ ebi0, const float* __restrict__ ebh0,
    const float* __restrict__ eW1, const float* __restrict__ eU1,
    const float* __restrict__ ebi1, const float* __restrict__ ebh1,
    const float* __restrict__ dW0, const float* __restrict__ dU0,
    const float* __restrict__ dbi0, const float* __restrict__ dbh0,
    const float* __restrict__ dW1, const float* __restrict__ dU1,
    const float* __restrict__ dbi1, const float* __restrict__ dbh1,
    const float* __restrict__ oW)
{
    int idx = blockIdx.x * 256 + threadIdx.x;  // 0..32767
    int k = idx >> 8, q = idx & 255;
    int s0 = q * 128 + k, s1 = (q + 256) * 128 + k;
    g_E0[idx] = make_uint2(pk(eW0[s0], eU0[s0]), pk(eW0[s1], eU0[s1]));
    g_E1[idx] = make_uint2(pk(eW1[s0], eU1[s0]), pk(eW1[s1], eU1[s1]));
    g_D0[idx] = make_uint2(pk(dW0[s0], dU0[s0]), pk(dW0[s1], dU0[s1]));
    g_D1[idx] = make_uint2(pk(dW1[s0], dU1[s0]), pk(dW1[s1], dU1[s1]));
    if (idx < 128 * 128) {
        int kk = idx >> 7, d = idx & 127;
        g_OW[kk * 128 + d] = oW[d * 128 + kk];
    }
    if (idx < 512) {
        g_bE0[idx] = ebi0[idx] + ebh0[idx];
        g_bE1[idx] = ebi1[idx] + ebh1[idx];
        g_bD0[idx] = dbi0[idx] + dbh0[idx];
        g_bD1[idx] = dbi1[idx] + dbh1[idx];
    }
}

__device__ __forceinline__ float sigf(float v)   { return 1.0f / (1.0f + __expf(-v)); }
__device__ __forceinline__ float tanhfa(float v) { return 1.0f - 2.0f / (__expf(2.0f * v) + 1.0f); }

__device__ __forceinline__ void spill(u64& acc, __half2 a) {
    float lo = __low2float(a), hi = __high2float(a);
    u64 p;
    asm("mov.b64 %0, {%1,%2};" : "=l"(p) : "f"(lo), "f"(hi));
    asm("add.rn.f32x2 %0, %1, %2;" : "=l"(acc) : "l"(acc), "l"(p));
}
__device__ __forceinline__ float fin(u64 acc, float b) {
    float lo, hi;
    asm("mov.b64 {%0,%1}, %2;" : "=f"(lo), "=f"(hi) : "l"(acc));
    return lo + hi + b;
}
__device__ __forceinline__ __half2 h2(u32 v) { return *(__half2*)&v; }

// 2 rows x 2 cols over 128 k. wq: base+q, stride 256/k. xh: 64 uint4 (2k each).
__device__ __forceinline__ void gemm2(
    const uint2* __restrict__ wq, const uint4* __restrict__ xh,
    float b0, float b1, float* __restrict__ g, int q)
{
    u64 A0 = 0, A1 = 0, A2 = 0, A3 = 0;
    const __half2 z = __float2half2_rn(0.f);
#pragma unroll 4
    for (int c = 0; c < 16; c++) {
        __half2 e0 = z, e1 = z, e2 = z, e3 = z;
        __half2 o0 = z, o1 = z, o2 = z, o3 = z;
#pragma unroll
        for (int m = 0; m < 4; m++) {
            int mm = c * 4 + m;
            uint4 xv = xh[mm];                     // k=2mm (x,y rows) , k=2mm+1 (z,w)
            uint2 w0 = wq[(2 * mm) * 256];
            uint2 w1 = wq[(2 * mm + 1) * 256];
            e0 = __hfma2(h2(w0.x), h2(xv.x), e0);
            e1 = __hfma2(h2(w0.y), h2(xv.x), e1);
            e2 = __hfma2(h2(w0.x), h2(xv.y), e2);
            e3 = __hfma2(h2(w0.y), h2(xv.y), e3);
            o0 = __hfma2(h2(w1.x), h2(xv.z), o0);
            o1 = __hfma2(h2(w1.y), h2(xv.z), o1);
            o2 = __hfma2(h2(w1.x), h2(xv.w), o2);
            o3 = __hfma2(h2(w1.y), h2(xv.w), o3);
        }
        spill(A0, __hadd2(e0, o0)); spill(A1, __hadd2(e1, o1));
        spill(A2, __hadd2(e2, o2)); spill(A3, __hadd2(e3, o3));
    }
    g[q]        = fin(A0, b0);  g[q + 256]       = fin(A1, b1);
    g[512 + q]  = fin(A2, b0);  g[512 + q + 256] = fin(A3, b1);
}

__device__ __forceinline__ float2 act(const float* g, int bb, int nn, float c) {
    float gi = g[bb * 512 + nn],       gf = g[bb * 512 + nn + 128];
    float gg = g[bb * 512 + nn + 256], go = g[bb * 512 + nn + 384];
    float cn = sigf(gf) * c + sigf(gi) * tanhfa(gg);
    return make_float2(cn, sigf(go) * tanhfa(cn));
}

#define GBAR() asm volatile("bar.sync %0, 256;" :: "r"(grp + 1) : "memory")

__global__ void __launch_bounds__(512, 1) lstm_main(
    const float* __restrict__ x, const float* __restrict__ out_b,
    float* __restrict__ out)
{
    __shared__ __align__(16) uint4 s_xh0[2][64];   // [grp]: 2k per uint4, (r0,r1)
    __shared__ __align__(16) uint4 s_xh1[2][64];
    __shared__ float s_g[2][2 * 512];
    __shared__ __align__(16) float s_h1f[2][2 * 128];

    const int tid = threadIdx.x;
    const int grp = tid >> 8;
    const int q   = tid & 255;
    const int bb  = q >> 7, nn = q & 127;
    const int row = blockIdx.x * 4 + grp * 2 + bb;

    const float bE0a = g_bE0[q], bE0b = g_bE0[q + 256];
    const float bE1a = g_bE1[q], bE1b = g_bE1[q + 256];
    const float bD0a = g_bD0[q], bD0b = g_bD0[q + 256];
    const float bD1a = g_bD1[q], bD1b = g_bD1[q + 256];
    const uint4* xh0 = s_xh0[grp];
    const uint4* xh1 = s_xh1[grp];
    float* gg = s_g[grp];
    // owned uint slot: index (nn>>1)*4 + (nn&1)*2 + bb
    u32* w0p = (u32*)s_xh0[grp] + ((nn >> 1) * 4 + (nn & 1) * 2 + bb);
    u32* w1p = (u32*)s_xh1[grp] + ((nn >> 1) * 4 + (nn & 1) * 2 + bb);

    float c0 = 0.f, c1 = 0.f;
    __half h0 = __float2half(0.f), h1 = __float2half(0.f);
    const float* xb = x + (size_t)row * (Tt * 128) + nn;
    float xnext = xb[0];

    *w0p = pk(xnext, 0.f);
    *w1p = 0u;
    xnext = xb[128];
    GBAR();

    // ------------------------------ encoder ------------------------------
    for (int t = 0; t < Tt; t++) {
        gemm2(g_E0 + q, xh0, bE0a, bE0b, gg, q);
        GBAR();
        {
            float2 ch = act(gg, bb, nn, c0); c0 = ch.x;
            h0 = __float2half(ch.y);
            *w1p = (u32)__half_as_ushort(h0) | ((u32)__half_as_ushort(h1) << 16);
        }
        GBAR();
        gemm2(g_E1 + q, xh1, bE1a, bE1b, gg, q);
        GBAR();
        {
            float2 ch = act(gg, bb, nn, c1); c1 = ch.x;
            h1 = __float2half(ch.y);
            *w0p = pk(xnext, __half2float(h0));
            if (t + 2 < Tt) xnext = xb[(t + 2) * 128];
        }
        GBAR();
    }

    // decoder init: x0 = final h1; states zero
    c0 = 0.f; c1 = 0.f;
    *w0p = (u32)__half_as_ushort(h1);          // (x0=h1, h0=0)
    *w1p = 0u;
    h0 = __float2half(0.f); h1 = __float2half(0.f);
    GBAR();

    // ------------------------------ decoder ------------------------------
    float* ob_ = out + (size_t)row * (Tt * 128) + nn;
    const float obv = out_b[nn];
    float* h1f = s_h1f[grp];
    for (int t = 0; t < Tt; t++) {
        gemm2(g_D0 + q, xh0, bD0a, bD0b, gg, q);
        GBAR();
        {
            float2 ch = act(gg, bb, nn, c0); c0 = ch.x;
            h0 = __float2half(ch.y);
            *w1p = (u32)__half_as_ushort(h0) | ((u32)__half_as_ushort(h1) << 16);
        }
        GBAR();
        gemm2(g_D1 + q, xh1, bD1a, bD1b, gg, q);
        GBAR();
        {
            float2 ch = act(gg, bb, nn, c1); c1 = ch.x;
            h1 = __float2half(ch.y);
            *w0p = (u32)__half_as_ushort(h1) | ((u32)__half_as_ushort(h0) << 16);
            h1f[bb * 128 + nn] = ch.y;
        }
        GBAR();

        float acc = obv;
        const float4* hv = (const float4*)(h1f + bb * 128);
#pragma unroll 8
        for (int kk = 0; kk < 32; kk++) {
            float4 h4 = hv[kk];
            acc = fmaf(h4.x, g_OW[(kk * 4 + 0) * 128 + nn], acc);
            acc = fmaf(h4.y, g_OW[(kk * 4 + 1) * 128 + nn], acc);
            acc = fmaf(h4.z, g_OW[(kk * 4 + 2) * 128 + nn], acc);
            acc = fmaf(h4.w, g_OW[(kk * 4 + 3) * 128 + nn], acc);
        }
        ob_[t * 128] = acc;
    }
}

extern "C" void kernel_launch(void* const* d_in, const int* in_sizes, int n_in,
                              void* d_out, int out_size)
{
    prep_kernel<<<128, 256>>>(
        (const float*)d_in[1],  (const float*)d_in[2],  (const float*)d_in[3],
        (const float*)d_in[4],  (const float*)d_in[5],  (const float*)d_in[6],
        (const float*)d_in[7],  (const float*)d_in[8],  (const float*)d_in[9],
        (const float*)d_in[10], (const float*)d_in[11], (const float*)d_in[12],
        (const float*)d_in[13], (const float*)d_in[14], (const float*)d_in[15],
        (const float*)d_in[16], (const float*)d_in[17]);
    lstm_main<<<128, 512>>>((const float*)d_in[0], (const float*)d_in[18],
                            (float*)d_out);
}